// round 5
// baseline (speedup 1.0000x reference)
#include <cuda_runtime.h>
#include <cuda_bf16.h>
#include <cstdint>

#define R_    4
#define B_    512
#define T_    150
#define HD    32
#define K_    600
#define NSTEP 38              // k16 steps covering 608 (pad zeros)
#define KSW   308             // word (bf16x2) stride per row: 308 % 32 == 20 -> conflict-free

// device intermediates
__device__ float g_attf[B_ * K_];
__device__ float g_w1t[K_ * 128];     // W1 transposed [k][c], filled by camA's y==4 plane

// ---------------- helpers ----------------
__device__ __forceinline__ uint32_t packbf(float lo, float hi) {
    uint32_t r; asm("cvt.rn.satfinite.bf16x2.f32 %0, %1, %2;" : "=r"(r) : "f"(hi), "f"(lo)); return r;
}
__device__ __forceinline__ uint32_t mul2(uint32_t a, uint32_t b) {
    uint32_t r; asm("mul.rn.bf16x2 %0, %1, %2;" : "=r"(r) : "r"(a), "r"(b)); return r;
}
__device__ __forceinline__ uint32_t tanh2(uint32_t a) {
    uint32_t r; asm("tanh.approx.bf16x2 %0, %1;" : "=r"(r) : "r"(a)); return r;
}
__device__ __forceinline__ void mma16816(float* d,
    uint32_t a0, uint32_t a1, uint32_t a2, uint32_t a3,
    uint32_t b0, uint32_t b1)
{
    asm volatile(
        "mma.sync.aligned.m16n8k16.row.col.f32.bf16.bf16.f32 "
        "{%0,%1,%2,%3}, {%4,%5,%6,%7}, {%8,%9}, {%0,%1,%2,%3};"
        : "+f"(d[0]), "+f"(d[1]), "+f"(d[2]), "+f"(d[3])
        : "r"(a0), "r"(a1), "r"(a2), "r"(a3), "r"(b0), "r"(b1));
}

// ---------------- kernel A ----------------
// grid (300, 5), block 256.
//   y in [0,4): compute plane r=y; CTA covers 256 m-rows (8 warps x 32 rows)
//   y == 4   : side-job, 300 CTAs x 256 thr transpose W1 into g_w1t (one elem each)
// smem (words of bf16x2): wc[32][308] | g[3][308] | W[32] | Wh[32]
#define SMW_WC 0
#define SMW_G  (HD * KSW)                       // 9856 words
#define SM_W   ((SMW_G + 3 * KSW) * 4)          // byte offset of W_s
#define SM_WH  (SM_W + 128)
#define SM_TOT (SM_WH + 128)                    // 43968 bytes

__global__ __launch_bounds__(256, 2)
void camA(const float* __restrict__ feats,
          const float* __restrict__ a,
          const float* __restrict__ W,
          const float* __restrict__ Wc,
          const float* __restrict__ Wh,
          const float* __restrict__ W1)
{
    const int tid = threadIdx.x;

    if (blockIdx.y == 4) {                      // W1 transpose side-job
        int idx = blockIdx.x * 256 + tid;       // exactly 300*256 = 76800 elems
        int k = idx >> 7;
        int c = idx & 127;
        g_w1t[idx] = W1[c * K_ + k];
        return;
    }

    extern __shared__ uint32_t smw[];
    uint32_t* wc_w = smw + SMW_WC;
    uint32_t* g_w  = smw + SMW_G;
    float*    W_s  = (float*)((char*)smw + SM_W);
    float*    Wh_s = (float*)((char*)smw + SM_WH);

    const int r  = blockIdx.y;
    const int m0 = blockIdx.x * 256;
    const int b0 = m0 / T_;

    // stage Wc[r] -> bf16x2 words, rows padded to 308 words (pad = 0)
    {
        const float2* src = (const float2*)(Wc + r * HD * K_);
        for (int j = tid; j < HD * KSW; j += 256) {
            int c  = j / KSW;
            int kp = j - c * KSW;
            uint32_t v = 0u;
            if (kp < K_ / 2) {
                float2 p = src[c * (K_ / 2) + kp];
                v = packbf(p.x, p.y);
            }
            wc_w[j] = v;
        }
    }
    // stage g rows b0..b0+2 as bf16x2, zero-padded
    for (int j = tid; j < 3 * KSW; j += 256) {
        int jb = j / KSW;
        int kp = j - jb * KSW;
        uint32_t v = 0u;
        int b = b0 + jb;
        if (kp < K_ / 2 && b < B_) {
            float2 p = *(const float2*)(feats + b * K_ + 2 * kp);
            v = packbf(p.x, p.y);
        }
        g_w[j] = v;
    }
    if (tid < HD) { W_s[tid] = W[r * HD + tid]; Wh_s[tid] = Wh[r * HD + tid]; }
    __syncthreads();

    const int w    = tid >> 5;
    const int lane = tid & 31;
    const int qid  = lane >> 2;
    const int qk   = lane & 3;

    // 4 rows per thread-position: m0 + w*32 + qid + 8i
    int   bb[4], tt[4];
    float f[4];
    uint32_t x2[4];
    const uint32_t* gp[4];
    const float ar = __ldg(a + r);
    #pragma unroll
    for (int i = 0; i < 4; i++) {
        int row = m0 + w * 32 + qid + 8 * i;
        bb[i] = row / T_;
        tt[i] = row - bb[i] * T_;
        f[i]  = __ldg(feats + (r * B_ + bb[i]) * T_ + tt[i]);
        float x = ar * f[i];
        x2[i] = packbf(x, x);
        gp[i] = g_w + (bb[i] - b0) * KSW + qk;
    }

    const uint32_t* wcp = wc_w + qid * KSW + qk;

    float d[2][4][4];
    #pragma unroll
    for (int t = 0; t < 2; t++)
        #pragma unroll
        for (int g = 0; g < 4; g++)
            #pragma unroll
            for (int i = 0; i < 4; i++) d[t][g][i] = 0.0f;

    #pragma unroll 2
    for (int s = 0; s < NSTEP; s++) {
        const int kw = s * 8;
        uint32_t aa[4][2];                        // [row i][lo/hi]
        #pragma unroll
        for (int i = 0; i < 4; i++) {
            aa[i][0] = tanh2(mul2(x2[i], gp[i][kw]));
            aa[i][1] = tanh2(mul2(x2[i], gp[i][kw + 4]));
        }
        #pragma unroll
        for (int g = 0; g < 4; g++) {
            uint32_t bf0 = wcp[g * 8 * KSW + kw];
            uint32_t bf1 = wcp[g * 8 * KSW + kw + 4];
            mma16816(d[0][g], aa[0][0], aa[1][0], aa[0][1], aa[1][1], bf0, bf1);
            mma16816(d[1][g], aa[2][0], aa[3][0], aa[2][1], aa[3][1], bf0, bf1);
        }
    }

    // epilogue: p[i] = sum_c relu(D + f*W)*Wh ; rows i=2t (d[..][0,1]) and i=2t+1 (d[..][2,3])
    float p[4] = {0.f, 0.f, 0.f, 0.f};
    #pragma unroll
    for (int g = 0; g < 4; g++) {
        float2 Wp  = *(const float2*)(W_s  + g * 8 + qk * 2);
        float2 Whp = *(const float2*)(Wh_s + g * 8 + qk * 2);
        #pragma unroll
        for (int t = 0; t < 2; t++) {
            p[2*t]   += fmaxf(fmaf(f[2*t],   Wp.x, d[t][g][0]), 0.f) * Whp.x
                      + fmaxf(fmaf(f[2*t],   Wp.y, d[t][g][1]), 0.f) * Whp.y;
            p[2*t+1] += fmaxf(fmaf(f[2*t+1], Wp.x, d[t][g][2]), 0.f) * Whp.x
                      + fmaxf(fmaf(f[2*t+1], Wp.y, d[t][g][3]), 0.f) * Whp.y;
        }
    }
    #pragma unroll
    for (int i = 0; i < 4; i++) {
        p[i] += __shfl_xor_sync(0xffffffffu, p[i], 1);
        p[i] += __shfl_xor_sync(0xffffffffu, p[i], 2);
    }
    if (qk == 0) {
        #pragma unroll
        for (int i = 0; i < 4; i++)
            g_attf[bb[i] * K_ + r * T_ + tt[i]] = p[i] + f[i];
    }
}

// ---------------- kernel B: MLP 600->128->7, 4 batches per CTA ----------------
__global__ __launch_bounds__(256)
void camB(const float* __restrict__ b1,
          const float* __restrict__ W2,
          const float* __restrict__ b2,
          float* __restrict__ out)
{
    __shared__ __align__(16) float v_s[4 * K_];
    __shared__ float h_s[4 * 128];

    const int bg  = blockIdx.x;
    const int tid = threadIdx.x;

    {
        const float4* src = (const float4*)(g_attf + bg * 4 * K_);
        float4* dst = (float4*)v_s;
        #pragma unroll
        for (int i = tid; i < 4 * K_ / 4; i += 256) dst[i] = src[i];
    }
    __syncthreads();

    // thread: c = tid&127, batch pair jh = tid>>7 (batches 2jh, 2jh+1)
    {
        const int c  = tid & 127;
        const int jh = tid >> 7;
        const float* v0 = v_s + (2 * jh)     * K_;
        const float* v1 = v_s + (2 * jh + 1) * K_;
        float a0 = 0.f, a1 = 0.f;
        #pragma unroll 4
        for (int k = 0; k < K_; k++) {
            float w1 = __ldg(g_w1t + k * 128 + c);
            a0 = fmaf(w1, v0[k], a0);
            a1 = fmaf(w1, v1[k], a1);
        }
        float bb = __ldg(b1 + c);
        h_s[(2 * jh)     * 128 + c] = a0 + bb;
        h_s[(2 * jh + 1) * 128 + c] = a1 + bb;
    }
    __syncthreads();

    if (tid < 28) {
        const int j = tid / 7;
        const int o = tid - j * 7;
        float s = __ldg(b2 + o);
        const float* hp = h_s + j * 128;
        const float* wp = W2 + o * 128;
        #pragma unroll 8
        for (int c = 0; c < 128; c++)
            s = fmaf(__ldg(wp + c), hp[c], s);
        out[(bg * 4 + j) * 7 + o] = s;
    }
}

// ---------------- launch ----------------
extern "C" void kernel_launch(void* const* d_in, const int* in_sizes, int n_in,
                              void* d_out, int out_size)
{
    const float* feats = (const float*)d_in[0];
    const float* a     = (const float*)d_in[1];
    const float* W     = (const float*)d_in[2];
    const float* Wc    = (const float*)d_in[3];
    const float* Wh    = (const float*)d_in[4];
    const float* W1    = (const float*)d_in[5];
    const float* b1    = (const float*)d_in[6];
    const float* W2    = (const float*)d_in[7];
    const float* b2    = (const float*)d_in[8];
    float* out = (float*)d_out;

    cudaFuncSetAttribute(camA, cudaFuncAttributeMaxDynamicSharedMemorySize, SM_TOT);

    dim3 gridA(300, 5);
    camA<<<gridA, 256, SM_TOT>>>(feats, a, W, Wc, Wh, W1);
    camB<<<B_ / 4, 256>>>(b1, W2, b2, out);
}

// round 6
// speedup vs baseline: 1.1828x; 1.1828x over previous
#include <cuda_runtime.h>
#include <cuda_bf16.h>
#include <cstdint>

#define R_    4
#define B_    512
#define T_    150
#define HD    32
#define K_    600
#define NSTEP 38              // k16 steps covering 608 (pad zeros)
#define KSW   308             // word (bf16x2) stride per row: 308 % 32 == 20 -> conflict-free

// device intermediate
__device__ float g_attf[B_ * K_];

// ---------------- helpers ----------------
__device__ __forceinline__ uint32_t packbf(float lo, float hi) {
    uint32_t r; asm("cvt.rn.satfinite.bf16x2.f32 %0, %1, %2;" : "=r"(r) : "f"(hi), "f"(lo)); return r;
}
__device__ __forceinline__ uint32_t mul2(uint32_t a, uint32_t b) {
    uint32_t r; asm("mul.rn.bf16x2 %0, %1, %2;" : "=r"(r) : "r"(a), "r"(b)); return r;
}
__device__ __forceinline__ uint32_t tanh2(uint32_t a) {
    uint32_t r; asm("tanh.approx.bf16x2 %0, %1;" : "=r"(r) : "r"(a)); return r;
}
__device__ __forceinline__ void mma16816(float* d,
    uint32_t a0, uint32_t a1, uint32_t a2, uint32_t a3,
    uint32_t b0, uint32_t b1)
{
    asm volatile(
        "mma.sync.aligned.m16n8k16.row.col.f32.bf16.bf16.f32 "
        "{%0,%1,%2,%3}, {%4,%5,%6,%7}, {%8,%9}, {%0,%1,%2,%3};"
        : "+f"(d[0]), "+f"(d[1]), "+f"(d[2]), "+f"(d[3])
        : "r"(a0), "r"(a1), "r"(a2), "r"(a3), "r"(b0), "r"(b1));
}

// ---------------- kernel A (unchanged design) ----------------
// grid (300, 4), block 256: CTA covers 256 m-rows (8 warps x 32 rows), plane r = blockIdx.y
// smem (bf16x2 words): wc[32][308] | g[3][308] | W[32] | Wh[32]
#define SMW_WC 0
#define SMW_G  (HD * KSW)                       // 9856 words
#define SM_W   ((SMW_G + 3 * KSW) * 4)          // byte offset of W_s
#define SM_WH  (SM_W + 128)
#define SM_TOT (SM_WH + 128)                    // 43968 bytes

__global__ __launch_bounds__(256, 2)
void camA(const float* __restrict__ feats,
          const float* __restrict__ a,
          const float* __restrict__ W,
          const float* __restrict__ Wc,
          const float* __restrict__ Wh)
{
    const int tid = threadIdx.x;

    extern __shared__ uint32_t smw[];
    uint32_t* wc_w = smw + SMW_WC;
    uint32_t* g_w  = smw + SMW_G;
    float*    W_s  = (float*)((char*)smw + SM_W);
    float*    Wh_s = (float*)((char*)smw + SM_WH);

    const int r  = blockIdx.y;
    const int m0 = blockIdx.x * 256;
    const int b0 = m0 / T_;

    // stage Wc[r] -> bf16x2 words, rows padded to 308 words (pad = 0)
    {
        const float2* src = (const float2*)(Wc + r * HD * K_);
        for (int j = tid; j < HD * KSW; j += 256) {
            int c  = j / KSW;
            int kp = j - c * KSW;
            uint32_t v = 0u;
            if (kp < K_ / 2) {
                float2 p = src[c * (K_ / 2) + kp];
                v = packbf(p.x, p.y);
            }
            wc_w[j] = v;
        }
    }
    // stage g rows b0..b0+2 as bf16x2, zero-padded
    for (int j = tid; j < 3 * KSW; j += 256) {
        int jb = j / KSW;
        int kp = j - jb * KSW;
        uint32_t v = 0u;
        int b = b0 + jb;
        if (kp < K_ / 2 && b < B_) {
            float2 p = *(const float2*)(feats + b * K_ + 2 * kp);
            v = packbf(p.x, p.y);
        }
        g_w[j] = v;
    }
    if (tid < HD) { W_s[tid] = W[r * HD + tid]; Wh_s[tid] = Wh[r * HD + tid]; }
    __syncthreads();

    const int w    = tid >> 5;
    const int lane = tid & 31;
    const int qid  = lane >> 2;
    const int qk   = lane & 3;

    // 4 rows per thread-position: m0 + w*32 + qid + 8i
    int   bb[4], tt[4];
    float f[4];
    uint32_t x2[4];
    const uint32_t* gp[4];
    const float ar = __ldg(a + r);
    #pragma unroll
    for (int i = 0; i < 4; i++) {
        int row = m0 + w * 32 + qid + 8 * i;
        bb[i] = row / T_;
        tt[i] = row - bb[i] * T_;
        f[i]  = __ldg(feats + (r * B_ + bb[i]) * T_ + tt[i]);
        float x = ar * f[i];
        x2[i] = packbf(x, x);
        gp[i] = g_w + (bb[i] - b0) * KSW + qk;
    }

    const uint32_t* wcp = wc_w + qid * KSW + qk;

    float d[2][4][4];
    #pragma unroll
    for (int t = 0; t < 2; t++)
        #pragma unroll
        for (int g = 0; g < 4; g++)
            #pragma unroll
            for (int i = 0; i < 4; i++) d[t][g][i] = 0.0f;

    #pragma unroll 2
    for (int s = 0; s < NSTEP; s++) {
        const int kw = s * 8;
        uint32_t aa[4][2];
        #pragma unroll
        for (int i = 0; i < 4; i++) {
            aa[i][0] = tanh2(mul2(x2[i], gp[i][kw]));
            aa[i][1] = tanh2(mul2(x2[i], gp[i][kw + 4]));
        }
        #pragma unroll
        for (int g = 0; g < 4; g++) {
            uint32_t bf0 = wcp[g * 8 * KSW + kw];
            uint32_t bf1 = wcp[g * 8 * KSW + kw + 4];
            mma16816(d[0][g], aa[0][0], aa[1][0], aa[0][1], aa[1][1], bf0, bf1);
            mma16816(d[1][g], aa[2][0], aa[3][0], aa[2][1], aa[3][1], bf0, bf1);
        }
    }

    // epilogue
    float p[4] = {0.f, 0.f, 0.f, 0.f};
    #pragma unroll
    for (int g = 0; g < 4; g++) {
        float2 Wp  = *(const float2*)(W_s  + g * 8 + qk * 2);
        float2 Whp = *(const float2*)(Wh_s + g * 8 + qk * 2);
        #pragma unroll
        for (int t = 0; t < 2; t++) {
            p[2*t]   += fmaxf(fmaf(f[2*t],   Wp.x, d[t][g][0]), 0.f) * Whp.x
                      + fmaxf(fmaf(f[2*t],   Wp.y, d[t][g][1]), 0.f) * Whp.y;
            p[2*t+1] += fmaxf(fmaf(f[2*t+1], Wp.x, d[t][g][2]), 0.f) * Whp.x
                      + fmaxf(fmaf(f[2*t+1], Wp.y, d[t][g][3]), 0.f) * Whp.y;
        }
    }
    #pragma unroll
    for (int i = 0; i < 4; i++) {
        p[i] += __shfl_xor_sync(0xffffffffu, p[i], 1);
        p[i] += __shfl_xor_sync(0xffffffffu, p[i], 2);
    }
    if (qk == 0) {
        #pragma unroll
        for (int i = 0; i < 4; i++)
            g_attf[bb[i] * K_ + r * T_ + tt[i]] = p[i] + f[i];
    }
}

// ---------------- kernel B: MLP 600->128->7 ----------------
// grid 128, block 512. Thread = (c = tid&127, jh = (tid>>7)&1, kh = tid>>8).
// Each thread: 2 batches (2jh, 2jh+1), K-half [kh*300, kh*300+300), W1 natural
// row-major rows read as float4 LDG (vector, L1-resident).
__global__ __launch_bounds__(512)
void camB(const float* __restrict__ W1,
          const float* __restrict__ b1,
          const float* __restrict__ W2,
          const float* __restrict__ b2,
          float* __restrict__ out)
{
    __shared__ __align__(16) float v_s[4 * K_];
    __shared__ float h_s[4][128];
    __shared__ float h_p[4][128];

    const int bg  = blockIdx.x;
    const int tid = threadIdx.x;

    {
        const float4* src = (const float4*)(g_attf + bg * 4 * K_);
        float4* dst = (float4*)v_s;
        #pragma unroll
        for (int i = tid; i < 4 * K_ / 4; i += 512) dst[i] = src[i];
    }
    __syncthreads();

    const int c  = tid & 127;
    const int jh = (tid >> 7) & 1;
    const int kh = tid >> 8;

    {
        const float* w1p = W1 + c * K_ + kh * 300;
        const float* v0  = v_s + (2 * jh)     * K_ + kh * 300;
        const float* v1  = v_s + (2 * jh + 1) * K_ + kh * 300;
        float a0 = 0.f, a1 = 0.f, b0a = 0.f, b1a = 0.f;
        #pragma unroll 5
        for (int k0 = 0; k0 < 300; k0 += 4) {
            float4 wv = *(const float4*)(w1p + k0);
            float4 p  = *(const float4*)(v0 + k0);
            float4 q  = *(const float4*)(v1 + k0);
            a0  = fmaf(wv.x, p.x, fmaf(wv.y, p.y, a0));
            b0a = fmaf(wv.z, p.z, fmaf(wv.w, p.w, b0a));
            a1  = fmaf(wv.x, q.x, fmaf(wv.y, q.y, a1));
            b1a = fmaf(wv.z, q.z, fmaf(wv.w, q.w, b1a));
        }
        a0 += b0a;
        a1 += b1a;
        if (kh == 1) {
            h_p[2 * jh][c]     = a0;
            h_p[2 * jh + 1][c] = a1;
        } else {
            h_s[2 * jh][c]     = a0;
            h_s[2 * jh + 1][c] = a1;
        }
    }
    __syncthreads();

    if (kh == 0) {
        float bb = __ldg(b1 + c);
        h_s[2 * jh][c]     += h_p[2 * jh][c] + bb;
        h_s[2 * jh + 1][c] += h_p[2 * jh + 1][c] + bb;
    }
    __syncthreads();

    if (tid < 28) {
        const int j = tid / 7;
        const int o = tid - j * 7;
        float s = __ldg(b2 + o);
        const float* hp = &h_s[j][0];
        const float* wp = W2 + o * 128;
        #pragma unroll 8
        for (int cc = 0; cc < 128; cc++)
            s = fmaf(__ldg(wp + cc), hp[cc], s);
        out[(bg * 4 + j) * 7 + o] = s;
    }
}

// ---------------- launch ----------------
extern "C" void kernel_launch(void* const* d_in, const int* in_sizes, int n_in,
                              void* d_out, int out_size)
{
    const float* feats = (const float*)d_in[0];
    const float* a     = (const float*)d_in[1];
    const float* W     = (const float*)d_in[2];
    const float* Wc    = (const float*)d_in[3];
    const float* Wh    = (const float*)d_in[4];
    const float* W1    = (const float*)d_in[5];
    const float* b1    = (const float*)d_in[6];
    const float* W2    = (const float*)d_in[7];
    const float* b2    = (const float*)d_in[8];
    float* out = (float*)d_out;

    cudaFuncSetAttribute(camA, cudaFuncAttributeMaxDynamicSharedMemorySize, SM_TOT);

    dim3 gridA(300, 4);
    camA<<<gridA, 256, SM_TOT>>>(feats, a, W, Wc, Wh);
    camB<<<B_ / 4, 512>>>(W1, b1, W2, b2, out);
}

// round 7
// speedup vs baseline: 1.2305x; 1.0403x over previous
#include <cuda_runtime.h>
#include <cuda_bf16.h>
#include <cstdint>

#define R_    4
#define B_    512
#define T_    150
#define HD    32
#define K_    600
#define NSTEP 38              // k16 steps covering 608 (pad zeros)
#define KSW   308             // bf16x2 words per row: 308 % 32 == 20 -> conflict-free
#define NCTA  296             // one full wave at occ 2 on 148 SMs
#define NTILE 1200            // 300 m-tiles x 4 r-planes

// device intermediate
__device__ float g_attf[B_ * K_];

// ---------------- helpers ----------------
__device__ __forceinline__ uint32_t packbf(float lo, float hi) {
    uint32_t r; asm("cvt.rn.satfinite.bf16x2.f32 %0, %1, %2;" : "=r"(r) : "f"(hi), "f"(lo)); return r;
}
__device__ __forceinline__ uint32_t mul2(uint32_t a, uint32_t b) {
    uint32_t r; asm("mul.rn.bf16x2 %0, %1, %2;" : "=r"(r) : "r"(a), "r"(b)); return r;
}
__device__ __forceinline__ uint32_t tanh2(uint32_t a) {
    uint32_t r; asm("tanh.approx.bf16x2 %0, %1;" : "=r"(r) : "r"(a)); return r;
}
__device__ __forceinline__ void mma16816(float* d,
    uint32_t a0, uint32_t a1, uint32_t a2, uint32_t a3,
    uint32_t b0, uint32_t b1)
{
    asm volatile(
        "mma.sync.aligned.m16n8k16.row.col.f32.bf16.bf16.f32 "
        "{%0,%1,%2,%3}, {%4,%5,%6,%7}, {%8,%9}, {%0,%1,%2,%3};"
        : "+f"(d[0]), "+f"(d[1]), "+f"(d[2]), "+f"(d[3])
        : "r"(a0), "r"(a1), "r"(a2), "r"(a3), "r"(b0), "r"(b1));
}

// ---------------- kernel A: persistent, 296 CTAs x 4-5 tiles ----------------
// smem (bf16x2 words): wc[32][308] | g[3][308] | W[32] | Wh[32]
#define SMW_WC 0
#define SMW_G  (HD * KSW)                       // 9856 words
#define SM_W   ((SMW_G + 3 * KSW) * 4)
#define SM_WH  (SM_W + 128)
#define SM_TOT (SM_WH + 128)                    // 43968 bytes

__global__ __launch_bounds__(256, 2)
void camA(const float* __restrict__ feats,
          const float* __restrict__ a,
          const float* __restrict__ W,
          const float* __restrict__ Wc,
          const float* __restrict__ Wh)
{
    extern __shared__ uint32_t smw[];
    uint32_t* wc_w = smw + SMW_WC;
    uint32_t* g_w  = smw + SMW_G;
    float*    W_s  = (float*)((char*)smw + SM_W);
    float*    Wh_s = (float*)((char*)smw + SM_WH);

    const int tid  = threadIdx.x;
    const int w    = tid >> 5;
    const int lane = tid & 31;
    const int qid  = lane >> 2;
    const int qk   = lane & 3;
    const int cta  = blockIdx.x;

    int prev_r = -1;

    #pragma unroll 1
    for (int kk = 0; kk < 5; kk++) {
        const int tile = cta + kk * NCTA;
        if (tile >= NTILE) break;
        const int r  = tile / 300;
        const int m0 = (tile - r * 300) * 256;
        const int b0 = m0 / T_;

        __syncthreads();                       // prior tile fully consumed

        if (r != prev_r) {
            // stage Wc[r] -> bf16x2 words, rows padded to 308 (pad=0)
            const float2* src = (const float2*)(Wc + r * HD * K_);
            for (int j = tid; j < HD * KSW; j += 256) {
                int c  = j / KSW;
                int kp = j - c * KSW;
                uint32_t v = 0u;
                if (kp < K_ / 2) {
                    float2 p = src[c * (K_ / 2) + kp];
                    v = packbf(p.x, p.y);
                }
                wc_w[j] = v;
            }
            if (tid < HD) { W_s[tid] = W[r * HD + tid]; Wh_s[tid] = Wh[r * HD + tid]; }
            prev_r = r;
        }
        // stage g rows b0..b0+2 (zero-padded)
        for (int j = tid; j < 3 * KSW; j += 256) {
            int jb = j / KSW;
            int kp = j - jb * KSW;
            uint32_t v = 0u;
            int b = b0 + jb;
            if (kp < K_ / 2 && b < B_) {
                float2 p = *(const float2*)(feats + b * K_ + 2 * kp);
                v = packbf(p.x, p.y);
            }
            g_w[j] = v;
        }
        __syncthreads();

        // per-thread row setup: rows m0 + w*32 + qid + 8i
        int   bb[4], tt[4];
        float f[4];
        uint32_t x2[4];
        const uint32_t* gp[4];
        const float ar = __ldg(a + r);
        #pragma unroll
        for (int i = 0; i < 4; i++) {
            int row = m0 + w * 32 + qid + 8 * i;
            bb[i] = row / T_;
            tt[i] = row - bb[i] * T_;
            f[i]  = __ldg(feats + (r * B_ + bb[i]) * T_ + tt[i]);
            float x = ar * f[i];
            x2[i] = packbf(x, x);
            gp[i] = g_w + (bb[i] - b0) * KSW + qk;
        }
        const uint32_t* wcp = wc_w + qid * KSW + qk;

        float d[2][4][4];
        #pragma unroll
        for (int t = 0; t < 2; t++)
            #pragma unroll
            for (int g = 0; g < 4; g++)
                #pragma unroll
                for (int i = 0; i < 4; i++) d[t][g][i] = 0.0f;

        #pragma unroll 2
        for (int s = 0; s < NSTEP; s++) {
            const int kw = s * 8;
            uint32_t aa[4][2];
            #pragma unroll
            for (int i = 0; i < 4; i++) {
                aa[i][0] = tanh2(mul2(x2[i], gp[i][kw]));
                aa[i][1] = tanh2(mul2(x2[i], gp[i][kw + 4]));
            }
            #pragma unroll
            for (int g = 0; g < 4; g++) {
                uint32_t bf0 = wcp[g * 8 * KSW + kw];
                uint32_t bf1 = wcp[g * 8 * KSW + kw + 4];
                mma16816(d[0][g], aa[0][0], aa[1][0], aa[0][1], aa[1][1], bf0, bf1);
                mma16816(d[1][g], aa[2][0], aa[3][0], aa[2][1], aa[3][1], bf0, bf1);
            }
        }

        // epilogue
        float p[4] = {0.f, 0.f, 0.f, 0.f};
        #pragma unroll
        for (int g = 0; g < 4; g++) {
            float2 Wp  = *(const float2*)(W_s  + g * 8 + qk * 2);
            float2 Whp = *(const float2*)(Wh_s + g * 8 + qk * 2);
            #pragma unroll
            for (int t = 0; t < 2; t++) {
                p[2*t]   += fmaxf(fmaf(f[2*t],   Wp.x, d[t][g][0]), 0.f) * Whp.x
                          + fmaxf(fmaf(f[2*t],   Wp.y, d[t][g][1]), 0.f) * Whp.y;
                p[2*t+1] += fmaxf(fmaf(f[2*t+1], Wp.x, d[t][g][2]), 0.f) * Whp.x
                          + fmaxf(fmaf(f[2*t+1], Wp.y, d[t][g][3]), 0.f) * Whp.y;
            }
        }
        #pragma unroll
        for (int i = 0; i < 4; i++) {
            p[i] += __shfl_xor_sync(0xffffffffu, p[i], 1);
            p[i] += __shfl_xor_sync(0xffffffffu, p[i], 2);
        }
        if (qk == 0) {
            #pragma unroll
            for (int i = 0; i < 4; i++)
                g_attf[bb[i] * K_ + r * T_ + tt[i]] = p[i] + f[i];
        }
    }
}

// ---------------- kernel B: MLP 600->128->7, warp-collective dots ----------------
// grid 128 (4 batches per CTA), block 256 (8 warps). Warp handles 16 c values;
// lanes stride k (coalesced LDG on W1 natural layout, stride-1 LDS on v).
__global__ __launch_bounds__(256)
void camB(const float* __restrict__ W1,
          const float* __restrict__ b1,
          const float* __restrict__ W2,
          const float* __restrict__ b2,
          float* __restrict__ out)
{
    __shared__ __align__(16) float v_s[4 * K_];
    __shared__ float h_s[4][128];

    const int bg   = blockIdx.x;
    const int tid  = threadIdx.x;
    const int w    = tid >> 5;
    const int lane = tid & 31;

    {
        const float4* src = (const float4*)(g_attf + bg * 4 * K_);
        float4* dst = (float4*)v_s;
        #pragma unroll
        for (int i = tid; i < 4 * K_ / 4; i += 256) dst[i] = src[i];
    }
    __syncthreads();

    #pragma unroll 1
    for (int ci = 0; ci < 16; ci++) {
        const int c = w * 16 + ci;
        const float* w1p = W1 + c * K_;
        float p0 = 0.f, p1 = 0.f, p2 = 0.f, p3 = 0.f;
        #pragma unroll
        for (int it = 0; it < 19; it++) {
            int k = it * 32 + lane;
            if (k < K_) {
                float w1 = __ldg(w1p + k);
                p0 = fmaf(w1, v_s[k],           p0);
                p1 = fmaf(w1, v_s[K_ + k],      p1);
                p2 = fmaf(w1, v_s[2 * K_ + k],  p2);
                p3 = fmaf(w1, v_s[3 * K_ + k],  p3);
            }
        }
        #pragma unroll
        for (int off = 16; off; off >>= 1) {
            p0 += __shfl_xor_sync(0xffffffffu, p0, off);
            p1 += __shfl_xor_sync(0xffffffffu, p1, off);
            p2 += __shfl_xor_sync(0xffffffffu, p2, off);
            p3 += __shfl_xor_sync(0xffffffffu, p3, off);
        }
        if (lane == 0) {
            float bb = __ldg(b1 + c);
            h_s[0][c] = p0 + bb;
            h_s[1][c] = p1 + bb;
            h_s[2][c] = p2 + bb;
            h_s[3][c] = p3 + bb;
        }
    }
    __syncthreads();

    if (tid < 28) {
        const int j = tid / 7;
        const int o = tid - j * 7;
        float s = __ldg(b2 + o);
        const float* hp = &h_s[j][0];
        const float* wp = W2 + o * 128;
        #pragma unroll 8
        for (int cc = 0; cc < 128; cc++)
            s = fmaf(__ldg(wp + cc), hp[cc], s);
        out[(bg * 4 + j) * 7 + o] = s;
    }
}

// ---------------- launch ----------------
extern "C" void kernel_launch(void* const* d_in, const int* in_sizes, int n_in,
                              void* d_out, int out_size)
{
    const float* feats = (const float*)d_in[0];
    const float* a     = (const float*)d_in[1];
    const float* W     = (const float*)d_in[2];
    const float* Wc    = (const float*)d_in[3];
    const float* Wh    = (const float*)d_in[4];
    const float* W1    = (const float*)d_in[5];
    const float* b1    = (const float*)d_in[6];
    const float* W2    = (const float*)d_in[7];
    const float* b2    = (const float*)d_in[8];
    float* out = (float*)d_out;

    cudaFuncSetAttribute(camA, cudaFuncAttributeMaxDynamicSharedMemorySize, SM_TOT);

    camA<<<NCTA, 256, SM_TOT>>>(feats, a, W, Wc, Wh);
    camB<<<B_ / 4, 256>>>(W1, b1, W2, b2, out);
}

// round 8
// speedup vs baseline: 1.2417x; 1.0091x over previous
#include <cuda_runtime.h>
#include <cuda_bf16.h>
#include <cstdint>

#define R_    4
#define B_    512
#define T_    150
#define HD    32
#define K_    600
#define NSTEP 38              // k16 steps covering 608 (pad zeros)
#define KSW   308             // bf16x2 words per row: 308 % 32 == 20 -> conflict-free
#define NCTA  444             // one full wave at occ 3 on 148 SMs
#define NTILE 1200            // 300 m-tiles x 4 r-planes

// device intermediate
__device__ float g_attf[B_ * K_];

// ---------------- helpers ----------------
__device__ __forceinline__ uint32_t packbf(float lo, float hi) {
    uint32_t r; asm("cvt.rn.satfinite.bf16x2.f32 %0, %1, %2;" : "=r"(r) : "f"(hi), "f"(lo)); return r;
}
__device__ __forceinline__ uint32_t mul2(uint32_t a, uint32_t b) {
    uint32_t r; asm("mul.rn.bf16x2 %0, %1, %2;" : "=r"(r) : "r"(a), "r"(b)); return r;
}
__device__ __forceinline__ uint32_t tanh2(uint32_t a) {
    uint32_t r; asm("tanh.approx.bf16x2 %0, %1;" : "=r"(r) : "r"(a)); return r;
}
__device__ __forceinline__ void mma16816(float* d,
    uint32_t a0, uint32_t a1, uint32_t a2, uint32_t a3,
    uint32_t b0, uint32_t b1)
{
    asm volatile(
        "mma.sync.aligned.m16n8k16.row.col.f32.bf16.bf16.f32 "
        "{%0,%1,%2,%3}, {%4,%5,%6,%7}, {%8,%9}, {%0,%1,%2,%3};"
        : "+f"(d[0]), "+f"(d[1]), "+f"(d[2]), "+f"(d[3])
        : "r"(a0), "r"(a1), "r"(a2), "r"(a3), "r"(b0), "r"(b1));
}

// ---------------- kernel A: persistent, 444 CTAs x <=3 tiles, occ 3 ----------------
// smem (bf16x2 words): wc[32][308] | g[3][308] | W[32] | Wh[32]
#define SMW_WC 0
#define SMW_G  (HD * KSW)                       // 9856 words
#define SM_W   ((SMW_G + 3 * KSW) * 4)
#define SM_WH  (SM_W + 128)
#define SM_TOT (SM_WH + 128)                    // 43968 bytes

__global__ __launch_bounds__(256, 3)
void camA(const float* __restrict__ feats,
          const float* __restrict__ a,
          const float* __restrict__ W,
          const float* __restrict__ Wc,
          const float* __restrict__ Wh)
{
    extern __shared__ uint32_t smw[];
    uint32_t* wc_w = smw + SMW_WC;
    uint32_t* g_w  = smw + SMW_G;
    float*    W_s  = (float*)((char*)smw + SM_W);
    float*    Wh_s = (float*)((char*)smw + SM_WH);

    const int tid  = threadIdx.x;
    const int w    = tid >> 5;
    const int lane = tid & 31;
    const int qid  = lane >> 2;
    const int qk   = lane & 3;
    const int cta  = blockIdx.x;

    int prev_r = -1;

    #pragma unroll 1
    for (int kk = 0; kk < 3; kk++) {
        const int tile = cta + kk * NCTA;
        if (tile >= NTILE) break;
        const int r  = tile / 300;
        const int m0 = (tile - r * 300) * 256;
        const int b0 = m0 / T_;

        __syncthreads();                       // prior tile fully consumed

        if (r != prev_r) {
            const float2* src = (const float2*)(Wc + r * HD * K_);
            for (int j = tid; j < HD * KSW; j += 256) {
                int c  = j / KSW;
                int kp = j - c * KSW;
                uint32_t v = 0u;
                if (kp < K_ / 2) {
                    float2 p = src[c * (K_ / 2) + kp];
                    v = packbf(p.x, p.y);
                }
                wc_w[j] = v;
            }
            if (tid < HD) { W_s[tid] = W[r * HD + tid]; Wh_s[tid] = Wh[r * HD + tid]; }
            prev_r = r;
        }
        for (int j = tid; j < 3 * KSW; j += 256) {
            int jb = j / KSW;
            int kp = j - jb * KSW;
            uint32_t v = 0u;
            int b = b0 + jb;
            if (kp < K_ / 2 && b < B_) {
                float2 p = *(const float2*)(feats + b * K_ + 2 * kp);
                v = packbf(p.x, p.y);
            }
            g_w[j] = v;
        }
        __syncthreads();

        // per-thread row setup: rows m0 + w*32 + qid + 8i
        float f[4];
        uint32_t x2[4];
        int gofs[4];
        const float ar = __ldg(a + r);
        #pragma unroll
        for (int i = 0; i < 4; i++) {
            int row = m0 + w * 32 + qid + 8 * i;
            int bbi = row / T_;
            int tti = row - bbi * T_;
            f[i]  = __ldg(feats + (r * B_ + bbi) * T_ + tti);
            float x = ar * f[i];
            x2[i] = packbf(x, x);
            gofs[i] = (bbi - b0) * KSW + qk;
        }
        const uint32_t* wcp = wc_w + qid * KSW + qk;

        float d[2][4][4];
        #pragma unroll
        for (int t = 0; t < 2; t++)
            #pragma unroll
            for (int g = 0; g < 4; g++)
                #pragma unroll
                for (int i = 0; i < 4; i++) d[t][g][i] = 0.0f;

        #pragma unroll 2
        for (int s = 0; s < NSTEP; s++) {
            const int kw = s * 8;
            uint32_t aa[4][2];
            #pragma unroll
            for (int i = 0; i < 4; i++) {
                aa[i][0] = tanh2(mul2(x2[i], g_w[gofs[i] + kw]));
                aa[i][1] = tanh2(mul2(x2[i], g_w[gofs[i] + kw + 4]));
            }
            #pragma unroll
            for (int g = 0; g < 4; g++) {
                uint32_t bf0 = wcp[g * 8 * KSW + kw];
                uint32_t bf1 = wcp[g * 8 * KSW + kw + 4];
                mma16816(d[0][g], aa[0][0], aa[1][0], aa[0][1], aa[1][1], bf0, bf1);
                mma16816(d[1][g], aa[2][0], aa[3][0], aa[2][1], aa[3][1], bf0, bf1);
            }
        }

        // epilogue (recompute row indices to save mainloop registers)
        float p[4] = {0.f, 0.f, 0.f, 0.f};
        #pragma unroll
        for (int g = 0; g < 4; g++) {
            float2 Wp  = *(const float2*)(W_s  + g * 8 + qk * 2);
            float2 Whp = *(const float2*)(Wh_s + g * 8 + qk * 2);
            #pragma unroll
            for (int t = 0; t < 2; t++) {
                p[2*t]   += fmaxf(fmaf(f[2*t],   Wp.x, d[t][g][0]), 0.f) * Whp.x
                          + fmaxf(fmaf(f[2*t],   Wp.y, d[t][g][1]), 0.f) * Whp.y;
                p[2*t+1] += fmaxf(fmaf(f[2*t+1], Wp.x, d[t][g][2]), 0.f) * Whp.x
                          + fmaxf(fmaf(f[2*t+1], Wp.y, d[t][g][3]), 0.f) * Whp.y;
            }
        }
        #pragma unroll
        for (int i = 0; i < 4; i++) {
            p[i] += __shfl_xor_sync(0xffffffffu, p[i], 1);
            p[i] += __shfl_xor_sync(0xffffffffu, p[i], 2);
        }
        if (qk == 0) {
            #pragma unroll
            for (int i = 0; i < 4; i++) {
                int row = m0 + w * 32 + qid + 8 * i;
                int bbi = row / T_;
                int tti = row - bbi * T_;
                g_attf[bbi * K_ + r * T_ + tti] = p[i] + f[i];
            }
        }
    }
}

// ---------------- kernel B: MLP 600->128->7, forced-MLP pipeline ----------------
// grid 128 (4 batches/CTA), block 512: thread = (c = tid&127, kq = tid>>7).
// k-quarter of 150 elems = 75 float2 steps, explicit 2-stage register pipeline.
__global__ __launch_bounds__(512, 1)
void camB(const float* __restrict__ W1,
          const float* __restrict__ b1,
          const float* __restrict__ W2,
          const float* __restrict__ b2,
          float* __restrict__ out)
{
    __shared__ __align__(16) float v_s[4 * K_];
    __shared__ float part_s[4][4][128];     // [kq][batch j][c]
    __shared__ float h_s[4][128];

    const int bg  = blockIdx.x;
    const int tid = threadIdx.x;

    {
        const float4* src = (const float4*)(g_attf + bg * 4 * K_);
        float4* dst = (float4*)v_s;
        #pragma unroll
        for (int i = tid; i < 4 * K_ / 4; i += 512) dst[i] = src[i];
    }
    __syncthreads();

    const int c  = tid & 127;
    const int kq = tid >> 7;
    const int kbase = kq * 150;             // 150 floats per quarter (600B, 8B-aligned)

    {
        const float2* wp = (const float2*)(W1 + c * K_ + kbase);
        const float2* vp0 = (const float2*)(v_s + 0 * K_ + kbase);
        const float2* vp1 = (const float2*)(v_s + 1 * K_ + kbase);
        const float2* vp2 = (const float2*)(v_s + 2 * K_ + kbase);
        const float2* vp3 = (const float2*)(v_s + 3 * K_ + kbase);

        float accx[4] = {0.f, 0.f, 0.f, 0.f};
        float accy[4] = {0.f, 0.f, 0.f, 0.f};

        // explicit 2-stage pipeline: prefetch it+1 while doing FMAs of it
        float2 wcur = __ldg(wp);
        float2 v0 = vp0[0], v1 = vp1[0], v2 = vp2[0], v3 = vp3[0];
        #pragma unroll 5
        for (int it = 0; it < 75; it++) {
            float2 wnxt, n0, n1, n2, n3;
            if (it + 1 < 75) {
                wnxt = __ldg(wp + it + 1);
                n0 = vp0[it + 1]; n1 = vp1[it + 1];
                n2 = vp2[it + 1]; n3 = vp3[it + 1];
            }
            accx[0] = fmaf(wcur.x, v0.x, accx[0]); accy[0] = fmaf(wcur.y, v0.y, accy[0]);
            accx[1] = fmaf(wcur.x, v1.x, accx[1]); accy[1] = fmaf(wcur.y, v1.y, accy[1]);
            accx[2] = fmaf(wcur.x, v2.x, accx[2]); accy[2] = fmaf(wcur.y, v2.y, accy[2]);
            accx[3] = fmaf(wcur.x, v3.x, accx[3]); accy[3] = fmaf(wcur.y, v3.y, accy[3]);
            wcur = wnxt;
            v0 = n0; v1 = n1; v2 = n2; v3 = n3;
        }
        #pragma unroll
        for (int j = 0; j < 4; j++)
            part_s[kq][j][c] = accx[j] + accy[j];
    }
    __syncthreads();

    // reduce partials: thread (c, j=kq) sums 4 kq-parts
    {
        const int j = kq;
        h_s[j][c] = part_s[0][j][c] + part_s[1][j][c]
                  + part_s[2][j][c] + part_s[3][j][c] + __ldg(b1 + c);
    }
    __syncthreads();

    if (tid < 28) {
        const int j = tid / 7;
        const int o = tid - j * 7;
        float s = __ldg(b2 + o);
        const float* hp = &h_s[j][0];
        const float* wp2 = W2 + o * 128;
        #pragma unroll 8
        for (int cc = 0; cc < 128; cc++)
            s = fmaf(__ldg(wp2 + cc), hp[cc], s);
        out[(bg * 4 + j) * 7 + o] = s;
    }
}

// ---------------- launch ----------------
extern "C" void kernel_launch(void* const* d_in, const int* in_sizes, int n_in,
                              void* d_out, int out_size)
{
    const float* feats = (const float*)d_in[0];
    const float* a     = (const float*)d_in[1];
    const float* W     = (const float*)d_in[2];
    const float* Wc    = (const float*)d_in[3];
    const float* Wh    = (const float*)d_in[4];
    const float* W1    = (const float*)d_in[5];
    const float* b1    = (const float*)d_in[6];
    const float* W2    = (const float*)d_in[7];
    const float* b2    = (const float*)d_in[8];
    float* out = (float*)d_out;

    cudaFuncSetAttribute(camA, cudaFuncAttributeMaxDynamicSharedMemorySize, SM_TOT);

    camA<<<NCTA, 256, SM_TOT>>>(feats, a, W, Wc, Wh);
    camB<<<B_ / 4, 512>>>(W1, b1, W2, b2, out);
}

// round 10
// speedup vs baseline: 1.3278x; 1.0694x over previous
#include <cuda_runtime.h>
#include <cuda_bf16.h>
#include <cstdint>

#define R_    4
#define B_    512
#define T_    150
#define HD    32
#define K_    600
#define NSTEP 38              // k16 steps covering 608 (pad zeros)
#define KSW   308             // bf16x2 words per row: 308 % 32 == 20 -> conflict-free
#define NCTA  296             // one full wave at occ 2 on 148 SMs
#define NTILE 1200            // 300 m-tiles x 4 r-planes
#define NTTOT 1224            // + 24 W1-transpose pseudo-tiles

// device intermediates
__device__ float g_attf[B_ * K_];
__device__ float g_w1t[K_ * 128];     // W1 transposed [k][c]

// ---------------- helpers ----------------
__device__ __forceinline__ uint32_t packbf(float lo, float hi) {
    uint32_t r; asm("cvt.rn.satfinite.bf16x2.f32 %0, %1, %2;" : "=r"(r) : "f"(hi), "f"(lo)); return r;
}
__device__ __forceinline__ uint32_t mul2(uint32_t a, uint32_t b) {
    uint32_t r; asm("mul.rn.bf16x2 %0, %1, %2;" : "=r"(r) : "r"(a), "r"(b)); return r;
}
__device__ __forceinline__ uint32_t tanh2(uint32_t a) {
    uint32_t r; asm("tanh.approx.bf16x2 %0, %1;" : "=r"(r) : "r"(a)); return r;
}
__device__ __forceinline__ void mma16816(float* d,
    uint32_t a0, uint32_t a1, uint32_t a2, uint32_t a3,
    uint32_t b0, uint32_t b1)
{
    asm volatile(
        "mma.sync.aligned.m16n8k16.row.col.f32.bf16.bf16.f32 "
        "{%0,%1,%2,%3}, {%4,%5,%6,%7}, {%8,%9}, {%0,%1,%2,%3};"
        : "+f"(d[0]), "+f"(d[1]), "+f"(d[2]), "+f"(d[3])
        : "r"(a0), "r"(a1), "r"(a2), "r"(a3), "r"(b0), "r"(b1));
}

// ---------------- kernel A: persistent, 296 CTAs x 5 tiles (r7 config) ----------------
// smem (bf16x2 words): wc[32][308] | g[3][308] | W[32] | Wh[32]
#define SMW_WC 0
#define SMW_G  (HD * KSW)                       // 9856 words
#define SM_W   ((SMW_G + 3 * KSW) * 4)
#define SM_WH  (SM_W + 128)
#define SM_TOT (SM_WH + 128)                    // 43968 bytes

__global__ __launch_bounds__(256, 2)
void camA(const float* __restrict__ feats,
          const float* __restrict__ a,
          const float* __restrict__ W,
          const float* __restrict__ Wc,
          const float* __restrict__ Wh,
          const float* __restrict__ W1)
{
    extern __shared__ uint32_t smw[];
    uint32_t* wc_w = smw + SMW_WC;
    uint32_t* g_w  = smw + SMW_G;
    float*    W_s  = (float*)((char*)smw + SM_W);
    float*    Wh_s = (float*)((char*)smw + SM_WH);

    const int tid  = threadIdx.x;
    const int w    = tid >> 5;
    const int lane = tid & 31;
    const int qid  = lane >> 2;
    const int qk   = lane & 3;
    const int cta  = blockIdx.x;

    int prev_r = -1;

    #pragma unroll 1
    for (int kk = 0; kk < 5; kk++) {
        const int tile = cta + kk * NCTA;
        if (tile >= NTTOT) break;

        __syncthreads();                       // prior tile fully consumed

        if (tile >= NTILE) {
            // W1-transpose pseudo-tile: 25 k-rows x 128 c (3200 elems), linear stores
            const int p = tile - NTILE;
            #pragma unroll
            for (int e = tid; e < 3200; e += 256) {
                int k = p * 25 + (e >> 7);
                int c = e & 127;
                g_w1t[p * 3200 + e] = W1[c * K_ + k];
            }
            continue;
        }

        const int r  = tile / 300;
        const int m0 = (tile - r * 300) * 256;
        const int b0 = m0 / T_;

        if (r != prev_r) {
            const float2* src = (const float2*)(Wc + r * HD * K_);
            for (int j = tid; j < HD * KSW; j += 256) {
                int c  = j / KSW;
                int kp = j - c * KSW;
                uint32_t v = 0u;
                if (kp < K_ / 2) {
                    float2 p = src[c * (K_ / 2) + kp];
                    v = packbf(p.x, p.y);
                }
                wc_w[j] = v;
            }
            if (tid < HD) { W_s[tid] = W[r * HD + tid]; Wh_s[tid] = Wh[r * HD + tid]; }
            prev_r = r;
        }
        for (int j = tid; j < 3 * KSW; j += 256) {
            int jb = j / KSW;
            int kp = j - jb * KSW;
            uint32_t v = 0u;
            int b = b0 + jb;
            if (kp < K_ / 2 && b < B_) {
                float2 p = *(const float2*)(feats + b * K_ + 2 * kp);
                v = packbf(p.x, p.y);
            }
            g_w[j] = v;
        }
        __syncthreads();

        // per-thread row setup: rows m0 + w*32 + qid + 8i
        int   bb[4], tt[4];
        float f[4];
        uint32_t x2[4];
        const uint32_t* gp[4];
        const float ar = __ldg(a + r);
        #pragma unroll
        for (int i = 0; i < 4; i++) {
            int row = m0 + w * 32 + qid + 8 * i;
            bb[i] = row / T_;
            tt[i] = row - bb[i] * T_;
            f[i]  = __ldg(feats + (r * B_ + bb[i]) * T_ + tt[i]);
            float x = ar * f[i];
            x2[i] = packbf(x, x);
            gp[i] = g_w + (bb[i] - b0) * KSW + qk;
        }
        const uint32_t* wcp = wc_w + qid * KSW + qk;

        float d[2][4][4];
        #pragma unroll
        for (int t = 0; t < 2; t++)
            #pragma unroll
            for (int g = 0; g < 4; g++)
                #pragma unroll
                for (int i = 0; i < 4; i++) d[t][g][i] = 0.0f;

        #pragma unroll 2
        for (int s = 0; s < NSTEP; s++) {
            const int kw = s * 8;
            uint32_t aa[4][2];
            #pragma unroll
            for (int i = 0; i < 4; i++) {
                aa[i][0] = tanh2(mul2(x2[i], gp[i][kw]));
                aa[i][1] = tanh2(mul2(x2[i], gp[i][kw + 4]));
            }
            #pragma unroll
            for (int g = 0; g < 4; g++) {
                uint32_t bf0 = wcp[g * 8 * KSW + kw];
                uint32_t bf1 = wcp[g * 8 * KSW + kw + 4];
                mma16816(d[0][g], aa[0][0], aa[1][0], aa[0][1], aa[1][1], bf0, bf1);
                mma16816(d[1][g], aa[2][0], aa[3][0], aa[2][1], aa[3][1], bf0, bf1);
            }
        }

        // epilogue
        float p[4] = {0.f, 0.f, 0.f, 0.f};
        #pragma unroll
        for (int g = 0; g < 4; g++) {
            float2 Wp  = *(const float2*)(W_s  + g * 8 + qk * 2);
            float2 Whp = *(const float2*)(Wh_s + g * 8 + qk * 2);
            #pragma unroll
            for (int t = 0; t < 2; t++) {
                p[2*t]   += fmaxf(fmaf(f[2*t],   Wp.x, d[t][g][0]), 0.f) * Whp.x
                          + fmaxf(fmaf(f[2*t],   Wp.y, d[t][g][1]), 0.f) * Whp.y;
                p[2*t+1] += fmaxf(fmaf(f[2*t+1], Wp.x, d[t][g][2]), 0.f) * Whp.x
                          + fmaxf(fmaf(f[2*t+1], Wp.y, d[t][g][3]), 0.f) * Whp.y;
            }
        }
        #pragma unroll
        for (int i = 0; i < 4; i++) {
            p[i] += __shfl_xor_sync(0xffffffffu, p[i], 1);
            p[i] += __shfl_xor_sync(0xffffffffu, p[i], 2);
        }
        if (qk == 0) {
            #pragma unroll
            for (int i = 0; i < 4; i++)
                g_attf[bb[i] * K_ + r * T_ + tt[i]] = p[i] + f[i];
        }
    }
}

// ---------------- kernel B: MLP 600->128->7, coalesced W1T + forced MLP ----------------
// grid 128 (4 batches/CTA), block 512: thread = (c = tid&127, kq = tid>>7).
// W1T reads: lanes span contiguous c -> 128B coalesced LDG, L2-hot.
__global__ __launch_bounds__(512, 1)
void camB(const float* __restrict__ b1,
          const float* __restrict__ W2,
          const float* __restrict__ b2,
          float* __restrict__ out)
{
    __shared__ __align__(16) float v_s[4 * K_];
    __shared__ float part_s[4][4][128];     // [kq][batch j][c]
    __shared__ float h_s[4][128];

    const int bg  = blockIdx.x;
    const int tid = threadIdx.x;

    {
        const float4* src = (const float4*)(g_attf + bg * 4 * K_);
        float4* dst = (float4*)v_s;
        #pragma unroll
        for (int i = tid; i < 4 * K_ / 4; i += 512) dst[i] = src[i];
    }
    __syncthreads();

    const int c  = tid & 127;
    const int kq = tid >> 7;
    const int kbase = kq * 150;

    {
        const float* wp = g_w1t + kbase * 128 + c;       // stride 128 floats per k
        const float2* vp0 = (const float2*)(v_s + 0 * K_ + kbase);
        const float2* vp1 = (const float2*)(v_s + 1 * K_ + kbase);
        const float2* vp2 = (const float2*)(v_s + 2 * K_ + kbase);
        const float2* vp3 = (const float2*)(v_s + 3 * K_ + kbase);

        float accx[4] = {0.f, 0.f, 0.f, 0.f};
        float accy[4] = {0.f, 0.f, 0.f, 0.f};

        #pragma unroll 5
        for (int it = 0; it < 75; it++) {
            float wx = __ldg(wp + (2 * it) * 128);        // coalesced across lanes
            float wy = __ldg(wp + (2 * it + 1) * 128);
            float2 v0 = vp0[it];                          // broadcast LDS.64
            float2 v1 = vp1[it];
            float2 v2 = vp2[it];
            float2 v3 = vp3[it];
            accx[0] = fmaf(wx, v0.x, accx[0]); accy[0] = fmaf(wy, v0.y, accy[0]);
            accx[1] = fmaf(wx, v1.x, accx[1]); accy[1] = fmaf(wy, v1.y, accy[1]);
            accx[2] = fmaf(wx, v2.x, accx[2]); accy[2] = fmaf(wy, v2.y, accy[2]);
            accx[3] = fmaf(wx, v3.x, accx[3]); accy[3] = fmaf(wy, v3.y, accy[3]);
        }
        #pragma unroll
        for (int j = 0; j < 4; j++)
            part_s[kq][j][c] = accx[j] + accy[j];
    }
    __syncthreads();

    {
        const int j = kq;
        h_s[j][c] = part_s[0][j][c] + part_s[1][j][c]
                  + part_s[2][j][c] + part_s[3][j][c] + __ldg(b1 + c);
    }
    __syncthreads();

    if (tid < 28) {
        const int j = tid / 7;
        const int o = tid - j * 7;
        float s = __ldg(b2 + o);
        const float* hp = &h_s[j][0];
        const float* wp2 = W2 + o * 128;
        #pragma unroll 8
        for (int cc = 0; cc < 128; cc++)
            s = fmaf(__ldg(wp2 + cc), hp[cc], s);
        out[(bg * 4 + j) * 7 + o] = s;
    }
}

// ---------------- launch ----------------
extern "C" void kernel_launch(void* const* d_in, const int* in_sizes, int n_in,
                              void* d_out, int out_size)
{
    const float* feats = (const float*)d_in[0];
    const float* a     = (const float*)d_in[1];
    const float* W     = (const float*)d_in[2];
    const float* Wc    = (const float*)d_in[3];
    const float* Wh    = (const float*)d_in[4];
    const float* W1    = (const float*)d_in[5];
    const float* b1    = (const float*)d_in[6];
    const float* W2    = (const float*)d_in[7];
    const float* b2    = (const float*)d_in[8];
    float* out = (float*)d_out;

    cudaFuncSetAttribute(camA, cudaFuncAttributeMaxDynamicSharedMemorySize, SM_TOT);

    camA<<<NCTA, 256, SM_TOT>>>(feats, a, W, Wc, Wh, W1);
    camB<<<B_ / 4, 512>>>(b1, W2, b2, out);
}